// round 13
// baseline (speedup 1.0000x reference)
#include <cuda_runtime.h>

// RasterizePointsXYsBlending — flat scatter + 2-pixel-per-thread composite.
// B=2, P=2048, C=64, SIZE=128, K=8, RADIUS=1.5px, RAD_POW=2, TAU=1.
//
//  K1 prep (384 blocks x 256 thr):
//     blocks [0,128):  transpose src [B,C,P] -> srcT [B,P,C]; 2 tiles per
//                      block, 2 independent LDG.128 per thread (MLP=8).
//     blocks [128,384): scatter — one thread per (point, 4x4 bbox cell):
//                      <=1 exact inside-test, <=1 atomic append (chain depth 1).
//  K2 composite (512 blocks x (32,4)): each thread owns TWO pixels
//     (w and w+32) x 16 channels — two independent latency chains per
//     thread (counter loads, list loads, gathers all pairwise parallel).
//     Counter recycle: all read both counters, __syncthreads, cg0 clears.
//     cnt<=8: order-independent weights w_i = a_i*prod_{z_j<z_i}(1-a_j);
//     cold top-8 insertion fallback for cnt>8.

#define BN 2
#define PN 2048
#define CN 64
#define SZ 128
#define KN 8
#define BIGF 1e10f
// r_ndc = 1.5/128*2 = 3*2^-7 ; r2 = 9*2^-14 (exact fp32)
#define R2 0.00054931640625f

#define CAPP 16                       // per-pixel list capacity (mean ~0.9)
#define NPIX (BN * SZ * SZ)           // 32768
#define TRB 128                       // transpose blocks (2 tiles each)
#define SCB 256                       // scatter blocks (256*256 = BN*PN*16)

__device__ float  d_srcT[BN * PN * CN];   // src transposed to [b,p,c]
__device__ int    d_cnt[NPIX];            // per-pixel counts (invariant: 0)
__device__ float4 d_list[NPIX * CAPP];    // (z, alpha, bitcast idx, -)

// ---------------------------------------------------------------- kernel 1
__global__ __launch_bounds__(256)
void prep_kernel(const float* __restrict__ src, const float* __restrict__ pts)
{
    if (blockIdx.x < TRB) {
        // -------- transpose: 2 tiles/block, 2 independent LDG.128/thread --
        __shared__ float t[2][32][33];
        const int i  = threadIdx.x;
        const int y  = i >> 3;            // 0..31 (channel row in tile)
        const int xq = (i & 7) * 4;       // 0,4,...,28 (p quad)

        float4 v[2];
#pragma unroll
        for (int q = 0; q < 2; ++q) {
            const int tl = blockIdx.x + q * TRB;     // covers 256 tiles
            const int b  = tl >> 7;
            const int c0 = ((tl >> 6) & 1) * 32;
            const int p0 = (tl & 63) * 32;
            v[q] = *(const float4*)
                (src + ((size_t)(b * CN + c0 + y) << 11) + p0 + xq);
        }
#pragma unroll
        for (int q = 0; q < 2; ++q) {
            t[q][y][xq + 0] = v[q].x;
            t[q][y][xq + 1] = v[q].y;
            t[q][y][xq + 2] = v[q].z;
            t[q][y][xq + 3] = v[q].w;
        }
        __syncthreads();

        const int c  = i & 31;            // output lane = channel
        const int pq = i >> 5;            // 0..7 (p row group of 4)
#pragma unroll
        for (int q = 0; q < 2; ++q) {
            const int tl = blockIdx.x + q * TRB;
            const int b  = tl >> 7;
            const int c0 = ((tl >> 6) & 1) * 32;
            const int p0 = (tl & 63) * 32;
#pragma unroll
            for (int r = 0; r < 4; ++r) {
                const int p = pq * 4 + r;
                d_srcT[((size_t)(b * PN + p0 + p) << 6) + c0 + c] =
                    t[q][c][p];
            }
        }
    } else {
        // ------- scatter: one thread per (point, 4x4 bbox cell) ----------
        const int s = (blockIdx.x - TRB) * 256 + threadIdx.x;
        const int cell = s & 15;
        const int rx   = cell & 3;
        const int ry   = cell >> 2;
        const int gp   = s >> 4;               // global point id
        const int b    = gp >> 11;
        const int p    = gp & (PN - 1);

        const float px = -pts[gp * 3 + 0];     // sign flip from forward
        const float py = -pts[gp * 3 + 1];
        const float pz =  pts[gp * 3 + 2];

        // pixel coords of the point: ndc(i) = 1-(2i+1)/128
        const float u = (1.0f - px) * 64.0f - 0.5f;   // w
        const float v = (1.0f - py) * 64.0f - 0.5f;   // h

        // radius 1.5 px + fp margin; bbox spans <=4 cells per axis
        const int wlo = max(0,      (int)ceilf (u - 1.6f));
        const int whi = min(SZ - 1, (int)floorf(u + 1.6f));
        const int hlo = max(0,      (int)ceilf (v - 1.6f));
        const int hhi = min(SZ - 1, (int)floorf(v + 1.6f));

        const int w = wlo + rx;
        const int h = hlo + ry;
        if (w <= whi && h <= hhi) {
            const float ndcy = 1.0f - (2.0f * (float)h + 1.0f) / 128.0f;
            const float ndcx = 1.0f - (2.0f * (float)w + 1.0f) / 128.0f;
            const float dx = ndcx - px;
            const float dy = ndcy - py;
            // mul/mul/add, non-fused: matches reference rounding exactly
            const float d2 =
                __fadd_rn(__fmul_rn(dx, dx), __fmul_rn(dy, dy));
            if (d2 <= R2) {
                // alpha with the reference's exact op sequence
                float dist = __fdiv_rn(d2, R2);
                dist = fminf(fmaxf(dist, 0.001f), 1.0f);
                const float a = 1.0f - __fsqrt_rn(dist);

                const int pix  = ((b * SZ) + h) * SZ + w;
                const int slot = atomicAdd(&d_cnt[pix], 1);
                if (slot < CAPP)
                    d_list[pix * CAPP + slot] =
                        make_float4(pz, a, __int_as_float(p), 0.0f);
            }
        }
    }
}

// ---------------------------------------------------------------- kernel 2
// Block (32,4): lane = w within a 64-wide half-row; each thread owns
// pixels (w, w+32) x 16 channels. grid = BN*SZ*2 = 512 blocks.
__global__ __launch_bounds__(128)
void composite_kernel(float* __restrict__ out)
{
    const int wt = blockIdx.x & 1;            // 64-wide half of the row
    const int h  = (blockIdx.x >> 1) & (SZ - 1);
    const int b  = blockIdx.x >> 8;
    const int x  = threadIdx.x;
    const int cg = threadIdx.y;               // channel group: 16 channels
    const int w0 = wt * 64 + x;
    const int pix0 = ((b * SZ) + h) * SZ + w0;
    const int pix1 = pix0 + 32;

    // both counter loads issued in parallel; read-before-clear block-wide.
    const int c0raw = d_cnt[pix0];
    const int c1raw = d_cnt[pix1];
    __syncthreads();
    if (cg == 0) { d_cnt[pix0] = 0; d_cnt[pix1] = 0; }
    const int cnt0 = min(c0raw, CAPP);
    const int cnt1 = min(c1raw, CAPP);

    float acc0[16], acc1[16];
#pragma unroll
    for (int j = 0; j < 16; ++j) { acc0[j] = 0.0f; acc1[j] = 0.0f; }

    const float* sbase = d_srcT + (((size_t)b * PN) << 6) + cg * 16;

    auto process = [&](int pix, int cnt, float* acc) {
        const float4* lp = d_list + pix * CAPP;
        if (cnt <= KN) {
            // common path: all points selected; order-independent weights
            for (int i = 0; i < cnt; ++i) {
                const float4 ei = lp[i];
                float wi = ei.y;                          // a_i
                for (int j = 0; j < cnt; ++j) {
                    if (j == i) continue;
                    const float4 ej = lp[j];
                    if (ej.x < ei.x) wi *= (1.0f - ej.y);
                }
                if (wi > 0.0f) {
                    const float4* s4 = (const float4*)
                        (sbase + ((size_t)__float_as_int(ei.z) << 6));
#pragma unroll
                    for (int q = 0; q < 4; ++q) {
                        const float4 v = s4[q];
                        acc[4 * q + 0] = fmaf(wi, v.x, acc[4 * q + 0]);
                        acc[4 * q + 1] = fmaf(wi, v.y, acc[4 * q + 1]);
                        acc[4 * q + 2] = fmaf(wi, v.z, acc[4 * q + 2]);
                        acc[4 * q + 3] = fmaf(wi, v.w, acc[4 * q + 3]);
                    }
                }
            }
        } else {
            // cold path: top-8 by z (insertion), then sequential cumprod
            float zb[KN], ab[KN];
            int   ib[KN];
#pragma unroll
            for (int k = 0; k < KN; ++k) { zb[k] = BIGF; ab[k] = 0.0f; ib[k] = 0; }
            for (int i = 0; i < cnt; ++i) {
                const float4 e = lp[i];
                if (e.x < zb[KN - 1]) {
                    float cz = e.x, ca = e.y;
                    int   ci = __float_as_int(e.z);
                    bool  ins = false;
#pragma unroll
                    for (int k = 0; k < KN; ++k) {
                        bool sw = ins | (cz < zb[k]);
                        if (sw) {
                            float tz = zb[k]; zb[k] = cz; cz = tz;
                            float ta = ab[k]; ab[k] = ca; ca = ta;
                            int   ti = ib[k]; ib[k] = ci; ci = ti;
                            ins = true;
                        }
                    }
                }
            }
            float T = 1.0f;
#pragma unroll
            for (int k = 0; k < KN; ++k) {
                if (zb[k] < BIGF) {
                    const float wi = ab[k] * T;
                    T = T * (1.0f - ab[k]);
                    if (wi > 0.0f) {
                        const float4* s4 = (const float4*)
                            (sbase + ((size_t)ib[k] << 6));
#pragma unroll
                        for (int q = 0; q < 4; ++q) {
                            const float4 v = s4[q];
                            acc[4 * q + 0] = fmaf(wi, v.x, acc[4 * q + 0]);
                            acc[4 * q + 1] = fmaf(wi, v.y, acc[4 * q + 1]);
                            acc[4 * q + 2] = fmaf(wi, v.z, acc[4 * q + 2]);
                            acc[4 * q + 3] = fmaf(wi, v.w, acc[4 * q + 3]);
                        }
                    }
                }
            }
        }
    };

    process(pix0, cnt0, acc0);
    process(pix1, cnt1, acc1);

    // out[b,c,h,w]; warp stores two coalesced 128B segments per plane
    float* ob = out + (((size_t)(b * CN + cg * 16)) * SZ + h) * SZ + w0;
#pragma unroll
    for (int j = 0; j < 16; ++j) {
        ob[(size_t)j * SZ * SZ]      = acc0[j];
        ob[(size_t)j * SZ * SZ + 32] = acc1[j];
    }
}

// ---------------------------------------------------------------- launch
extern "C" void kernel_launch(void* const* d_in, const int* in_sizes, int n_in,
                              void* d_out, int out_size)
{
    const float* pts = (const float*)d_in[0];  // [B,P,3]
    const float* src = (const float*)d_in[1];  // [B,C,P]
    float* out = (float*)d_out;                // [B,C,H,W]

    prep_kernel<<<TRB + SCB, 256>>>(src, pts);
    composite_kernel<<<BN * SZ * 2, dim3(32, 4)>>>(out);
}

// round 14
// speedup vs baseline: 1.1844x; 1.1844x over previous
#include <cuda_runtime.h>

// RasterizePointsXYsBlending — flat scatter + smem-staged composite.
// B=2, P=2048, C=64, SIZE=128, K=8, RADIUS=1.5px, RAD_POW=2, TAU=1.
//
//  K1 prep (384 blocks x 256 thr):  [R12-verbatim]
//     blocks [0,128):  transpose src [B,C,P] -> srcT [B,P,C]; 2 tiles per
//                      block, 2 independent LDG.128 per thread (MLP=8).
//     blocks [128,384): scatter — one thread per (point, 4x4 bbox cell):
//                      <=1 exact inside-test, <=1 atomic append (depth-1 chain).
//  K2 composite (1024 blocks x (32,4)) — R12 mapping + bulk list staging:
//     the block's 32 pixel-lists (slots 0..7) are one contiguous 4KB slab;
//     staged to smem with 2 coalesced independent LDG.128/thread, in
//     parallel with the counter load. After one __syncthreads (also the
//     read-before-clear fence for the counters) the weight loop runs on
//     smem. cnt<=8: order-independent weights w_i = a_i*prod_{z_j<z_i}(1-a_j);
//     cnt>8 cold path reads the full global list (top-8 insertion).

#define BN 2
#define PN 2048
#define CN 64
#define SZ 128
#define KN 8
#define BIGF 1e10f
// r_ndc = 1.5/128*2 = 3*2^-7 ; r2 = 9*2^-14 (exact fp32)
#define R2 0.00054931640625f

#define CAPP 16                       // per-pixel list capacity (mean ~0.9)
#define NPIX (BN * SZ * SZ)           // 32768
#define TRB 128                       // transpose blocks (2 tiles each)
#define SCB 256                       // scatter blocks (256*256 = BN*PN*16)

__device__ float  d_srcT[BN * PN * CN];   // src transposed to [b,p,c]
__device__ int    d_cnt[NPIX];            // per-pixel counts (invariant: 0)
__device__ float4 d_list[NPIX * CAPP];    // (z, alpha, bitcast idx, -)

// ---------------------------------------------------------------- kernel 1
__global__ __launch_bounds__(256)
void prep_kernel(const float* __restrict__ src, const float* __restrict__ pts)
{
    if (blockIdx.x < TRB) {
        // -------- transpose: 2 tiles/block, 2 independent LDG.128/thread --
        __shared__ float t[2][32][33];
        const int i  = threadIdx.x;
        const int y  = i >> 3;            // 0..31 (channel row in tile)
        const int xq = (i & 7) * 4;       // 0,4,...,28 (p quad)

        float4 v[2];
#pragma unroll
        for (int q = 0; q < 2; ++q) {
            const int tl = blockIdx.x + q * TRB;     // covers 256 tiles
            const int b  = tl >> 7;
            const int c0 = ((tl >> 6) & 1) * 32;
            const int p0 = (tl & 63) * 32;
            v[q] = *(const float4*)
                (src + ((size_t)(b * CN + c0 + y) << 11) + p0 + xq);
        }
#pragma unroll
        for (int q = 0; q < 2; ++q) {
            t[q][y][xq + 0] = v[q].x;
            t[q][y][xq + 1] = v[q].y;
            t[q][y][xq + 2] = v[q].z;
            t[q][y][xq + 3] = v[q].w;
        }
        __syncthreads();

        const int c  = i & 31;            // output lane = channel
        const int pq = i >> 5;            // 0..7 (p row group of 4)
#pragma unroll
        for (int q = 0; q < 2; ++q) {
            const int tl = blockIdx.x + q * TRB;
            const int b  = tl >> 7;
            const int c0 = ((tl >> 6) & 1) * 32;
            const int p0 = (tl & 63) * 32;
#pragma unroll
            for (int r = 0; r < 4; ++r) {
                const int p = pq * 4 + r;
                d_srcT[((size_t)(b * PN + p0 + p) << 6) + c0 + c] =
                    t[q][c][p];
            }
        }
    } else {
        // ------- scatter: one thread per (point, 4x4 bbox cell) ----------
        const int s = (blockIdx.x - TRB) * 256 + threadIdx.x;
        const int cell = s & 15;
        const int rx   = cell & 3;
        const int ry   = cell >> 2;
        const int gp   = s >> 4;               // global point id
        const int b    = gp >> 11;
        const int p    = gp & (PN - 1);

        const float px = -pts[gp * 3 + 0];     // sign flip from forward
        const float py = -pts[gp * 3 + 1];
        const float pz =  pts[gp * 3 + 2];

        // pixel coords of the point: ndc(i) = 1-(2i+1)/128
        const float u = (1.0f - px) * 64.0f - 0.5f;   // w
        const float v = (1.0f - py) * 64.0f - 0.5f;   // h

        // radius 1.5 px + fp margin; bbox spans <=4 cells per axis
        const int wlo = max(0,      (int)ceilf (u - 1.6f));
        const int whi = min(SZ - 1, (int)floorf(u + 1.6f));
        const int hlo = max(0,      (int)ceilf (v - 1.6f));
        const int hhi = min(SZ - 1, (int)floorf(v + 1.6f));

        const int w = wlo + rx;
        const int h = hlo + ry;
        if (w <= whi && h <= hhi) {
            const float ndcy = 1.0f - (2.0f * (float)h + 1.0f) / 128.0f;
            const float ndcx = 1.0f - (2.0f * (float)w + 1.0f) / 128.0f;
            const float dx = ndcx - px;
            const float dy = ndcy - py;
            // mul/mul/add, non-fused: matches reference rounding exactly
            const float d2 =
                __fadd_rn(__fmul_rn(dx, dx), __fmul_rn(dy, dy));
            if (d2 <= R2) {
                // alpha with the reference's exact op sequence
                float dist = __fdiv_rn(d2, R2);
                dist = fminf(fmaxf(dist, 0.001f), 1.0f);
                const float a = 1.0f - __fsqrt_rn(dist);

                const int pix  = ((b * SZ) + h) * SZ + w;
                const int slot = atomicAdd(&d_cnt[pix], 1);
                if (slot < CAPP)
                    d_list[pix * CAPP + slot] =
                        make_float4(pz, a, __int_as_float(p), 0.0f);
            }
        }
    }
}

// ---------------------------------------------------------------- kernel 2
// Block (32,4): 32 pixels (lane = w) x 4 channel-groups (16 ch/thread).
// grid = BN*SZ*(SZ/32) = 1024 blocks.
__global__ __launch_bounds__(128)
void composite_kernel(float* __restrict__ out)
{
    __shared__ float4 s_list[KN][32];        // [slot][pixel], conflict-free

    const int wt = blockIdx.x & 3;
    const int h  = (blockIdx.x >> 2) & (SZ - 1);
    const int b  = blockIdx.x >> 9;
    const int x  = threadIdx.x;
    const int w  = wt * 32 + x;
    const int cg = threadIdx.y;              // channel group: 16 channels
    const int pix  = ((b * SZ) + h) * SZ + w;
    const int pix0 = ((b * SZ) + h) * SZ + wt * 32;   // block's first pixel

    // counter load + bulk list staging, all issued before the barrier.
    const int cnt_raw = d_cnt[pix];

    // stage slots 0..7 of the block's 32 pixel lists: 256 float4, 2/thread.
    const int tid = cg * 32 + x;             // 0..127
#pragma unroll
    for (int q = 0; q < 2; ++q) {
        const int j = tid * 2 + q;           // 0..255
        const int p = j >> 3;                // pixel within block
        const int s = j & 7;                 // slot
        s_list[s][p] = d_list[(size_t)(pix0 + p) * CAPP + s];
    }

    // read-before-clear fence (also publishes s_list)
    __syncthreads();
    if (cg == 0) d_cnt[pix] = 0;             // restore all-zero invariant
    const int cnt = min(cnt_raw, CAPP);

    float acc[16];
#pragma unroll
    for (int j = 0; j < 16; ++j) acc[j] = 0.0f;

    const float* sbase = d_srcT + (((size_t)b * PN) << 6) + cg * 16;
    auto gather = [&](int idx, float wi) {
        const float4* s4 = (const float4*)(sbase + ((size_t)idx << 6));
#pragma unroll
        for (int q = 0; q < 4; ++q) {
            const float4 v = s4[q];
            acc[4 * q + 0] = fmaf(wi, v.x, acc[4 * q + 0]);
            acc[4 * q + 1] = fmaf(wi, v.y, acc[4 * q + 1]);
            acc[4 * q + 2] = fmaf(wi, v.z, acc[4 * q + 2]);
            acc[4 * q + 3] = fmaf(wi, v.w, acc[4 * q + 3]);
        }
    };

    if (cnt <= KN) {
        // ---- common path: weights from smem, order-independent
        for (int i = 0; i < cnt; ++i) {
            const float4 ei = s_list[i][x];
            float wi = ei.y;                              // a_i
            for (int j = 0; j < cnt; ++j) {
                if (j == i) continue;
                const float4 ej = s_list[j][x];
                if (ej.x < ei.x) wi *= (1.0f - ej.y);
            }
            if (wi > 0.0f) gather(__float_as_int(ei.z), wi);
        }
    } else {
        // ---- cold path (P ~ 1e-7): full global list, top-8 insertion
        const float4* lp = d_list + (size_t)pix * CAPP;
        float zb[KN], ab[KN];
        int   ib[KN];
#pragma unroll
        for (int k = 0; k < KN; ++k) { zb[k] = BIGF; ab[k] = 0.0f; ib[k] = 0; }
        for (int i = 0; i < cnt; ++i) {
            const float4 e = lp[i];
            if (e.x < zb[KN - 1]) {
                float cz = e.x, ca = e.y;
                int   ci = __float_as_int(e.z);
                bool  ins = false;
#pragma unroll
                for (int k = 0; k < KN; ++k) {
                    bool sw = ins | (cz < zb[k]);
                    if (sw) {
                        float tz = zb[k]; zb[k] = cz; cz = tz;
                        float ta = ab[k]; ab[k] = ca; ca = ta;
                        int   ti = ib[k]; ib[k] = ci; ci = ti;
                        ins = true;
                    }
                }
            }
        }
        float T = 1.0f;
#pragma unroll
        for (int k = 0; k < KN; ++k) {
            if (zb[k] < BIGF) {
                const float wi = ab[k] * T;
                T = T * (1.0f - ab[k]);
                if (wi > 0.0f) gather(ib[k], wi);
            }
        }
    }

    // out[b,c,h,w]; lane = w -> coalesced 128B stores per channel plane
    float* ob = out + (((size_t)(b * CN + cg * 16)) * SZ + h) * SZ + w;
#pragma unroll
    for (int j = 0; j < 16; ++j)
        ob[(size_t)j * SZ * SZ] = acc[j];
}

// ---------------------------------------------------------------- launch
extern "C" void kernel_launch(void* const* d_in, const int* in_sizes, int n_in,
                              void* d_out, int out_size)
{
    const float* pts = (const float*)d_in[0];  // [B,P,3]
    const float* src = (const float*)d_in[1];  // [B,C,P]
    float* out = (float*)d_out;                // [B,C,H,W]

    prep_kernel<<<TRB + SCB, 256>>>(src, pts);
    composite_kernel<<<BN * SZ * (SZ / 32), dim3(32, 4)>>>(out);
}